// round 8
// baseline (speedup 1.0000x reference)
#include <cuda_runtime.h>
#include <cuda_bf16.h>

#define NMAX   50000
#define EMAX   800000
#define FEATN  128
#define POOLW  384   // 3*128
#define NGRAPH 128
#define SCAN_T 1024

// ---------------- scratch (static device globals; no allocation) -------------
__device__ __align__(256) float g_dis [NMAX];
__device__ __align__(256) int   g_cnt [NMAX];
__device__ __align__(256) int   g_fill[NMAX];
__device__ __align__(256) int   g_off [NMAX + 1];
__device__ __align__(256) int   g_src [EMAX];
__device__ __align__(256) float g_hs  [NMAX * FEATN];   // dis[r] * (x @ W)
__device__ __align__(256) float g_x1  [NMAX * FEATN];
__device__ __align__(256) float g_x2  [NMAX * FEATN];
__device__ __align__(256) float g_pool[NGRAPH * POOLW];

// ---------------- prep: counts, scan, fill, dis ------------------------------
__global__ void zero_kernel(int n) {
    int i = blockIdx.x * blockDim.x + threadIdx.x;
    if (i < NGRAPH * POOLW) g_pool[i] = 0.0f;
    if (i < n) { g_cnt[i] = 0; g_fill[i] = 0; }
}

__global__ void count_kernel(const int* __restrict__ ei_col, int E) {
    int e = blockIdx.x * blockDim.x + threadIdx.x;
    if (e < E) atomicAdd(&g_cnt[ei_col[e]], 1);
}

// single-block exclusive scan of g_cnt -> g_off; also dis = rsqrt(1+cnt)
__global__ __launch_bounds__(SCAN_T) void scan_kernel(int n) {
    __shared__ int ssum[SCAN_T];
    int tid = threadIdx.x;
    int chunk = (n + SCAN_T - 1) / SCAN_T;
    int lo = tid * chunk;
    int hi = min(lo + chunk, n);
    int s = 0;
    for (int i = lo; i < hi; i++) s += g_cnt[i];
    ssum[tid] = s;
    __syncthreads();
    for (int d = 1; d < SCAN_T; d <<= 1) {
        int v = (tid >= d) ? ssum[tid - d] : 0;
        __syncthreads();
        ssum[tid] += v;
        __syncthreads();
    }
    int base = (tid > 0) ? ssum[tid - 1] : 0;
    for (int i = lo; i < hi; i++) {
        g_off[i] = base;
        g_dis[i] = rsqrtf(1.0f + (float)g_cnt[i]);
        base += g_cnt[i];
    }
    if (tid == SCAN_T - 1) g_off[n] = base;
}

__global__ void fill_kernel(const int* __restrict__ ei, int E) {
    int e = blockIdx.x * blockDim.x + threadIdx.x;
    if (e < E) {
        int c = ei[E + e];
        int pos = g_off[c] + atomicAdd(&g_fill[c], 1);
        g_src[pos] = ei[e];
    }
}

// ---------------- GEMM: hs = dis * (X @ W) -----------------------------------
// tile: 128 rows x 128 cols, 256 threads; thread = 8x8 register tile.
// X staged transposed in smem. Row stride GM+4 keeps float4 LDS 16B-aligned.
#define GM 128
#define GK 32
__global__ __launch_bounds__(256) void gemm_layer_kernel(
    int xsel, const float* __restrict__ Xin, const float* __restrict__ W, int N)
{
    const float* X = (xsel == 0) ? Xin : (xsel == 1 ? g_x1 : g_x2);

    __shared__ float sXt[GK][GM + 4];   // [k][row], stride 132 (16B-aligned rows)
    __shared__ float sW [GK][FEATN];    // [k][col]

    int tid  = threadIdx.x;
    int tx   = tid & 15;      // col group: cols tx*8..+8
    int ty   = tid >> 4;      // row group: rows ty*8..+8
    int row0 = blockIdx.x * GM;

    float acc[8][8];
    #pragma unroll
    for (int i = 0; i < 8; i++)
        #pragma unroll
        for (int j = 0; j < 8; j++) acc[i][j] = 0.f;

    #pragma unroll
    for (int kc = 0; kc < FEATN; kc += GK) {
        // X chunk: 128x32 = 1024 float4, 4 per thread; store transposed
        #pragma unroll
        for (int i = 0; i < 4; i++) {
            int idx = tid + i * 256;       // 0..1023
            int r   = idx >> 3;            // 0..127
            int c4  = (idx & 7) * 4;       // 0..28
            float4 v = make_float4(0.f, 0.f, 0.f, 0.f);
            int gr = row0 + r;
            if (gr < N) v = *(const float4*)(X + (long)gr * FEATN + kc + c4);
            sXt[c4 + 0][r] = v.x;
            sXt[c4 + 1][r] = v.y;
            sXt[c4 + 2][r] = v.z;
            sXt[c4 + 3][r] = v.w;
        }
        // W chunk: 32x128 = 1024 float4, 4 per thread
        #pragma unroll
        for (int i = 0; i < 4; i++) {
            int idx = tid + i * 256;
            int r   = idx >> 5;            // 0..31
            int c4  = (idx & 31) * 4;
            *(float4*)(&sW[r][c4]) = *(const float4*)(W + (long)(kc + r) * FEATN + c4);
        }
        __syncthreads();

        #pragma unroll
        for (int k = 0; k < GK; k++) {
            float4 a0 = *(float4*)(&sXt[k][ty * 8]);
            float4 a1 = *(float4*)(&sXt[k][ty * 8 + 4]);
            float4 b0 = *(float4*)(&sW [k][tx * 8]);
            float4 b1 = *(float4*)(&sW [k][tx * 8 + 4]);
            float a[8] = {a0.x, a0.y, a0.z, a0.w, a1.x, a1.y, a1.z, a1.w};
            float b[8] = {b0.x, b0.y, b0.z, b0.w, b1.x, b1.y, b1.z, b1.w};
            #pragma unroll
            for (int i = 0; i < 8; i++)
                #pragma unroll
                for (int j = 0; j < 8; j++)
                    acc[i][j] += a[i] * b[j];
        }
        __syncthreads();
    }

    #pragma unroll
    for (int i = 0; i < 8; i++) {
        int gr = row0 + ty * 8 + i;
        if (gr < N) {
            float d = g_dis[gr];
            float4 h0, h1;
            h0.x = acc[i][0] * d; h0.y = acc[i][1] * d;
            h0.z = acc[i][2] * d; h0.w = acc[i][3] * d;
            h1.x = acc[i][4] * d; h1.y = acc[i][5] * d;
            h1.z = acc[i][6] * d; h1.w = acc[i][7] * d;
            float* p = g_hs + (long)gr * FEATN + tx * 8;
            *(float4*)(p)     = h0;
            *(float4*)(p + 4) = h1;
        }
    }
}

// ---------------- gather + finalize (fused) ----------------------------------
// warp per node: out = relu(dis[i]*(sum_in hs[r] + hs[i]) + b); pool += out
__global__ __launch_bounds__(256) void gather_kernel(
    const float* __restrict__ b, int outsel, float* __restrict__ x3out,
    const int* __restrict__ batch, int N, int pool_off)
{
    long idx = (long)blockIdx.x * blockDim.x + threadIdx.x;
    int i = (int)(idx >> 5);
    if (i >= N) return;
    int lane = (int)(idx & 31);
    int l4 = lane * 4;

    float* xnext = (outsel == 1) ? g_x1 : (outsel == 2 ? g_x2 : x3out);

    // self loop term (hs already carries dis[i])
    float4 accA = *(const float4*)(g_hs + (long)i * FEATN + l4);
    float4 accB = make_float4(0.f, 0.f, 0.f, 0.f);

    int s0 = g_off[i];
    int s1 = g_off[i + 1];
    int k = s0;
    // 8-way unroll, dual accumulators: 8 outstanding L2 loads, split FP chains
    for (; k + 8 <= s1; k += 8) {
        int r0 = g_src[k],   r1 = g_src[k+1], r2 = g_src[k+2], r3 = g_src[k+3];
        int r4 = g_src[k+4], r5 = g_src[k+5], r6 = g_src[k+6], r7 = g_src[k+7];
        float4 v0 = *(const float4*)(g_hs + (long)r0 * FEATN + l4);
        float4 v1 = *(const float4*)(g_hs + (long)r1 * FEATN + l4);
        float4 v2 = *(const float4*)(g_hs + (long)r2 * FEATN + l4);
        float4 v3 = *(const float4*)(g_hs + (long)r3 * FEATN + l4);
        float4 v4 = *(const float4*)(g_hs + (long)r4 * FEATN + l4);
        float4 v5 = *(const float4*)(g_hs + (long)r5 * FEATN + l4);
        float4 v6 = *(const float4*)(g_hs + (long)r6 * FEATN + l4);
        float4 v7 = *(const float4*)(g_hs + (long)r7 * FEATN + l4);
        accA.x += (v0.x + v1.x) + (v2.x + v3.x);
        accA.y += (v0.y + v1.y) + (v2.y + v3.y);
        accA.z += (v0.z + v1.z) + (v2.z + v3.z);
        accA.w += (v0.w + v1.w) + (v2.w + v3.w);
        accB.x += (v4.x + v5.x) + (v6.x + v7.x);
        accB.y += (v4.y + v5.y) + (v6.y + v7.y);
        accB.z += (v4.z + v5.z) + (v6.z + v7.z);
        accB.w += (v4.w + v5.w) + (v6.w + v7.w);
    }
    for (; k + 4 <= s1; k += 4) {
        int r0 = g_src[k], r1 = g_src[k+1], r2 = g_src[k+2], r3 = g_src[k+3];
        float4 v0 = *(const float4*)(g_hs + (long)r0 * FEATN + l4);
        float4 v1 = *(const float4*)(g_hs + (long)r1 * FEATN + l4);
        float4 v2 = *(const float4*)(g_hs + (long)r2 * FEATN + l4);
        float4 v3 = *(const float4*)(g_hs + (long)r3 * FEATN + l4);
        accA.x += (v0.x + v1.x) + (v2.x + v3.x);
        accA.y += (v0.y + v1.y) + (v2.y + v3.y);
        accA.z += (v0.z + v1.z) + (v2.z + v3.z);
        accA.w += (v0.w + v1.w) + (v2.w + v3.w);
    }
    for (; k < s1; k++) {
        int r = g_src[k];
        float4 v = *(const float4*)(g_hs + (long)r * FEATN + l4);
        accB.x += v.x; accB.y += v.y; accB.z += v.z; accB.w += v.w;
    }
    accA.x += accB.x; accA.y += accB.y; accA.z += accB.z; accA.w += accB.w;

    float d = g_dis[i];
    float4 bv = *(const float4*)(b + l4);
    float4 o;
    o.x = fmaxf(accA.x * d + bv.x, 0.f);
    o.y = fmaxf(accA.y * d + bv.y, 0.f);
    o.z = fmaxf(accA.z * d + bv.z, 0.f);
    o.w = fmaxf(accA.w * d + bv.w, 0.f);
    *(float4*)(xnext + (long)i * FEATN + l4) = o;

    int g = batch[i];
    float* p = g_pool + (long)g * POOLW + pool_off + l4;
    atomicAdd(p + 0, o.x);
    atomicAdd(p + 1, o.y);
    atomicAdd(p + 2, o.z);
    atomicAdd(p + 3, o.w);
}

__global__ void copy_pool_kernel(float* __restrict__ out) {
    int i = blockIdx.x * blockDim.x + threadIdx.x;
    if (i < NGRAPH * POOLW) out[i] = g_pool[i];
}

// ---------------- launch ------------------------------------------------------
extern "C" void kernel_launch(void* const* d_in, const int* in_sizes, int n_in,
                              void* d_out, int out_size)
{
    const float* x     = (const float*)d_in[0];
    const int*   ei    = (const int*)d_in[1];    // int32 (JAX x64 disabled)
    const int*   batch = (const int*)d_in[2];
    const float* W0    = (const float*)d_in[3];
    const float* b0    = (const float*)d_in[4];
    const float* W1    = (const float*)d_in[5];
    const float* b1    = (const float*)d_in[6];
    const float* W2    = (const float*)d_in[7];
    const float* b2    = (const float*)d_in[8];

    int N = in_sizes[0] / FEATN;     // 50000
    int E = in_sizes[1] / 2;         // 800000
    int pool_elems = NGRAPH * POOLW; // 49152

    float* out = (float*)d_out;
    float* x3  = out + pool_elems;

    // prep: zero, count, scan(+dis), fill  (CSR built once, reused 3x)
    zero_kernel<<<(N + 255) / 256, 256>>>(N);
    count_kernel<<<(E + 255) / 256, 256>>>(ei + E, E);
    scan_kernel<<<1, SCAN_T>>>(N);
    fill_kernel<<<(E + 255) / 256, 256>>>(ei, E);

    int gemm_blocks  = (N + GM - 1) / GM;
    long gat_threads = (long)N * 32;
    int gat_blocks   = (int)((gat_threads + 255) / 256);

    // layer 1
    gemm_layer_kernel<<<gemm_blocks, 256>>>(0, x, W0, N);
    gather_kernel<<<gat_blocks, 256>>>(b0, 1, nullptr, batch, N, 0);

    // layer 2
    gemm_layer_kernel<<<gemm_blocks, 256>>>(1, nullptr, W1, N);
    gather_kernel<<<gat_blocks, 256>>>(b1, 2, nullptr, batch, N, 128);

    // layer 3
    gemm_layer_kernel<<<gemm_blocks, 256>>>(2, nullptr, W2, N);
    gather_kernel<<<gat_blocks, 256>>>(b2, 3, x3, batch, N, 256);

    // pool -> d_out (plain stores only)
    copy_pool_kernel<<<(pool_elems + 255) / 256, 256>>>(out);
}

// round 9
// speedup vs baseline: 1.2978x; 1.2978x over previous
#include <cuda_runtime.h>
#include <cuda_bf16.h>

#define NMAX   50000
#define EMAX   800000
#define FEATN  128
#define POOLW  384   // 3*128
#define NGRAPH 128
#define SCAN_T 1024

// ---------------- scratch (static device globals; no allocation) -------------
__device__ __align__(256) float g_dis [NMAX];
__device__ __align__(256) int   g_cnt [NMAX];
__device__ __align__(256) int   g_fill[NMAX];
__device__ __align__(256) int   g_off [NMAX + 1];
__device__ __align__(256) int   g_src [EMAX];
__device__ __align__(256) float g_hs  [NMAX * FEATN];   // dis[r] * (x @ W)
__device__ __align__(256) float g_x1  [NMAX * FEATN];
__device__ __align__(256) float g_x2  [NMAX * FEATN];
__device__ __align__(256) float g_pool[NGRAPH * POOLW];

// ---------------- prep: counts, scan, fill, dis ------------------------------
__global__ void zero_kernel(int n) {
    int i = blockIdx.x * blockDim.x + threadIdx.x;
    if (i < NGRAPH * POOLW) g_pool[i] = 0.0f;
    if (i < n) { g_cnt[i] = 0; g_fill[i] = 0; }
}

__global__ void count_kernel(const int* __restrict__ ei_col, int E) {
    int e = blockIdx.x * blockDim.x + threadIdx.x;
    if (e < E) atomicAdd(&g_cnt[ei_col[e]], 1);
}

// single-block exclusive scan of g_cnt -> g_off; also dis = rsqrt(1+cnt)
__global__ __launch_bounds__(SCAN_T) void scan_kernel(int n) {
    __shared__ int ssum[SCAN_T];
    int tid = threadIdx.x;
    int chunk = (n + SCAN_T - 1) / SCAN_T;
    int lo = tid * chunk;
    int hi = min(lo + chunk, n);
    int s = 0;
    for (int i = lo; i < hi; i++) s += g_cnt[i];
    ssum[tid] = s;
    __syncthreads();
    for (int d = 1; d < SCAN_T; d <<= 1) {
        int v = (tid >= d) ? ssum[tid - d] : 0;
        __syncthreads();
        ssum[tid] += v;
        __syncthreads();
    }
    int base = (tid > 0) ? ssum[tid - 1] : 0;
    for (int i = lo; i < hi; i++) {
        g_off[i] = base;
        g_dis[i] = rsqrtf(1.0f + (float)g_cnt[i]);
        base += g_cnt[i];
    }
    if (tid == SCAN_T - 1) g_off[n] = base;
}

__global__ void fill_kernel(const int* __restrict__ ei, int E) {
    int e = blockIdx.x * blockDim.x + threadIdx.x;
    if (e < E) {
        int c = ei[E + e];
        int pos = g_off[c] + atomicAdd(&g_fill[c], 1);
        g_src[pos] = ei[e];
    }
}

// ---------------- GEMM: hs = dis * (X @ W)  (proven R6 tile) -----------------
// tile: 64 rows x 128 cols, 256 threads; thread = 8 rows x 4 cols.
#define TM 64
#define TK 32
__global__ __launch_bounds__(256) void gemm_layer_kernel(
    int xsel, const float* __restrict__ Xin, const float* __restrict__ W, int N)
{
    const float* X = (xsel == 0) ? Xin : (xsel == 1 ? g_x1 : g_x2);

    __shared__ float sX[TM][TK + 4];
    __shared__ float sW[TK][FEATN];

    int tid  = threadIdx.x;
    int row0 = blockIdx.x * TM;
    int cg   = tid & 31;
    int rg   = tid >> 5;

    float acc[8][4];
    #pragma unroll
    for (int i = 0; i < 8; i++)
        { acc[i][0]=0.f; acc[i][1]=0.f; acc[i][2]=0.f; acc[i][3]=0.f; }

    for (int kc = 0; kc < FEATN; kc += TK) {
        #pragma unroll
        for (int i = 0; i < 2; i++) {
            int idx = tid + i * 256;
            int r   = idx >> 3;
            int c4  = (idx & 7) * 4;
            float4 v = make_float4(0.f, 0.f, 0.f, 0.f);
            int gr = row0 + r;
            if (gr < N) v = *(const float4*)(X + (long)gr * FEATN + kc + c4);
            sX[r][c4]   = v.x; sX[r][c4+1] = v.y;
            sX[r][c4+2] = v.z; sX[r][c4+3] = v.w;
        }
        #pragma unroll
        for (int i = 0; i < 4; i++) {
            int idx = tid + i * 256;
            int r   = idx >> 5;
            int c4  = (idx & 31) * 4;
            *(float4*)(&sW[r][c4]) = *(const float4*)(W + (long)(kc + r) * FEATN + c4);
        }
        __syncthreads();

        #pragma unroll
        for (int k = 0; k < TK; k++) {
            float a[8];
            #pragma unroll
            for (int i = 0; i < 8; i++) a[i] = sX[rg * 8 + i][k];
            float4 b = *(float4*)(&sW[k][cg * 4]);
            #pragma unroll
            for (int i = 0; i < 8; i++) {
                acc[i][0] += a[i] * b.x;
                acc[i][1] += a[i] * b.y;
                acc[i][2] += a[i] * b.z;
                acc[i][3] += a[i] * b.w;
            }
        }
        __syncthreads();
    }

    #pragma unroll
    for (int i = 0; i < 8; i++) {
        int gr = row0 + rg * 8 + i;
        if (gr < N) {
            float d = g_dis[gr];
            float4 h;
            h.x = acc[i][0] * d; h.y = acc[i][1] * d;
            h.z = acc[i][2] * d; h.w = acc[i][3] * d;
            *(float4*)(g_hs + (long)gr * FEATN + cg * 4) = h;
        }
    }
}

// ---------------- gather + finalize (fused) ----------------------------------
// warp per node: out = relu(dis[i]*(sum_in hs[r] + hs[i]) + b); pool += out
__global__ __launch_bounds__(256) void gather_kernel(
    const float* __restrict__ b, int outsel, float* __restrict__ x3out,
    const int* __restrict__ batch, int N, int pool_off)
{
    long idx = (long)blockIdx.x * blockDim.x + threadIdx.x;
    int i = (int)(idx >> 5);
    if (i >= N) return;
    int lane = (int)(idx & 31);
    int l4 = lane * 4;

    float* xnext = (outsel == 1) ? g_x1 : (outsel == 2 ? g_x2 : x3out);

    // self loop term (hs already carries dis[i])
    float4 accA = *(const float4*)(g_hs + (long)i * FEATN + l4);
    float4 accB = make_float4(0.f, 0.f, 0.f, 0.f);

    int s0 = g_off[i];
    int s1 = g_off[i + 1];
    int k = s0;
    // 8-way unroll, dual accumulators: 8 outstanding L2 loads, split FP chains
    for (; k + 8 <= s1; k += 8) {
        int r0 = g_src[k],   r1 = g_src[k+1], r2 = g_src[k+2], r3 = g_src[k+3];
        int r4 = g_src[k+4], r5 = g_src[k+5], r6 = g_src[k+6], r7 = g_src[k+7];
        float4 v0 = *(const float4*)(g_hs + (long)r0 * FEATN + l4);
        float4 v1 = *(const float4*)(g_hs + (long)r1 * FEATN + l4);
        float4 v2 = *(const float4*)(g_hs + (long)r2 * FEATN + l4);
        float4 v3 = *(const float4*)(g_hs + (long)r3 * FEATN + l4);
        float4 v4 = *(const float4*)(g_hs + (long)r4 * FEATN + l4);
        float4 v5 = *(const float4*)(g_hs + (long)r5 * FEATN + l4);
        float4 v6 = *(const float4*)(g_hs + (long)r6 * FEATN + l4);
        float4 v7 = *(const float4*)(g_hs + (long)r7 * FEATN + l4);
        accA.x += (v0.x + v1.x) + (v2.x + v3.x);
        accA.y += (v0.y + v1.y) + (v2.y + v3.y);
        accA.z += (v0.z + v1.z) + (v2.z + v3.z);
        accA.w += (v0.w + v1.w) + (v2.w + v3.w);
        accB.x += (v4.x + v5.x) + (v6.x + v7.x);
        accB.y += (v4.y + v5.y) + (v6.y + v7.y);
        accB.z += (v4.z + v5.z) + (v6.z + v7.z);
        accB.w += (v4.w + v5.w) + (v6.w + v7.w);
    }
    for (; k + 4 <= s1; k += 4) {
        int r0 = g_src[k], r1 = g_src[k+1], r2 = g_src[k+2], r3 = g_src[k+3];
        float4 v0 = *(const float4*)(g_hs + (long)r0 * FEATN + l4);
        float4 v1 = *(const float4*)(g_hs + (long)r1 * FEATN + l4);
        float4 v2 = *(const float4*)(g_hs + (long)r2 * FEATN + l4);
        float4 v3 = *(const float4*)(g_hs + (long)r3 * FEATN + l4);
        accA.x += (v0.x + v1.x) + (v2.x + v3.x);
        accA.y += (v0.y + v1.y) + (v2.y + v3.y);
        accA.z += (v0.z + v1.z) + (v2.z + v3.z);
        accA.w += (v0.w + v1.w) + (v2.w + v3.w);
    }
    for (; k < s1; k++) {
        int r = g_src[k];
        float4 v = *(const float4*)(g_hs + (long)r * FEATN + l4);
        accB.x += v.x; accB.y += v.y; accB.z += v.z; accB.w += v.w;
    }
    accA.x += accB.x; accA.y += accB.y; accA.z += accB.z; accA.w += accB.w;

    float d = g_dis[i];
    float4 bv = *(const float4*)(b + l4);
    float4 o;
    o.x = fmaxf(accA.x * d + bv.x, 0.f);
    o.y = fmaxf(accA.y * d + bv.y, 0.f);
    o.z = fmaxf(accA.z * d + bv.z, 0.f);
    o.w = fmaxf(accA.w * d + bv.w, 0.f);
    *(float4*)(xnext + (long)i * FEATN + l4) = o;

    int g = batch[i];
    float* p = g_pool + (long)g * POOLW + pool_off + l4;
    atomicAdd(p + 0, o.x);
    atomicAdd(p + 1, o.y);
    atomicAdd(p + 2, o.z);
    atomicAdd(p + 3, o.w);
}

__global__ void copy_pool_kernel(float* __restrict__ out) {
    int i = blockIdx.x * blockDim.x + threadIdx.x;
    if (i < NGRAPH * POOLW) out[i] = g_pool[i];
}

// ---------------- launch ------------------------------------------------------
extern "C" void kernel_launch(void* const* d_in, const int* in_sizes, int n_in,
                              void* d_out, int out_size)
{
    const float* x     = (const float*)d_in[0];
    const int*   ei    = (const int*)d_in[1];    // int32 (JAX x64 disabled)
    const int*   batch = (const int*)d_in[2];
    const float* W0    = (const float*)d_in[3];
    const float* b0    = (const float*)d_in[4];
    const float* W1    = (const float*)d_in[5];
    const float* b1    = (const float*)d_in[6];
    const float* W2    = (const float*)d_in[7];
    const float* b2    = (const float*)d_in[8];

    int N = in_sizes[0] / FEATN;     // 50000
    int E = in_sizes[1] / 2;         // 800000
    int pool_elems = NGRAPH * POOLW; // 49152

    float* out = (float*)d_out;
    float* x3  = out + pool_elems;

    // prep: zero, count, scan(+dis), fill  (CSR built once, reused 3x)
    zero_kernel<<<(N + 255) / 256, 256>>>(N);
    count_kernel<<<(E + 255) / 256, 256>>>(ei + E, E);
    scan_kernel<<<1, SCAN_T>>>(N);
    fill_kernel<<<(E + 255) / 256, 256>>>(ei, E);

    int gemm_blocks  = (N + TM - 1) / TM;
    long gat_threads = (long)N * 32;
    int gat_blocks   = (int)((gat_threads + 255) / 256);

    // layer 1
    gemm_layer_kernel<<<gemm_blocks, 256>>>(0, x, W0, N);
    gather_kernel<<<gat_blocks, 256>>>(b0, 1, nullptr, batch, N, 0);

    // layer 2
    gemm_layer_kernel<<<gemm_blocks, 256>>>(1, nullptr, W1, N);
    gather_kernel<<<gat_blocks, 256>>>(b1, 2, nullptr, batch, N, 128);

    // layer 3
    gemm_layer_kernel<<<gemm_blocks, 256>>>(2, nullptr, W2, N);
    gather_kernel<<<gat_blocks, 256>>>(b2, 3, x3, batch, N, 256);

    // pool -> d_out (plain stores only)
    copy_pool_kernel<<<(pool_elems + 255) / 256, 256>>>(out);
}

// round 10
// speedup vs baseline: 1.5149x; 1.1672x over previous
#include <cuda_runtime.h>
#include <cuda_bf16.h>
#include <cstdint>

#define NMAX   50000
#define EMAX   800000
#define FEATN  128
#define POOLW  384   // 3*128
#define NGRAPH 128
#define SCAN_T 1024

// ---------------- scratch (static device globals; no allocation) -------------
__device__ __align__(256) float g_dis [NMAX];
__device__ __align__(256) int   g_cnt [NMAX];
__device__ __align__(256) int   g_fill[NMAX];
__device__ __align__(256) int   g_off [NMAX + 1];
__device__ __align__(256) int   g_src [EMAX];
__device__ __align__(256) float g_hs  [NMAX * FEATN];   // dis[r] * (x @ W)
__device__ __align__(256) float g_x1  [NMAX * FEATN];
__device__ __align__(256) float g_x2  [NMAX * FEATN];
__device__ __align__(256) float g_pool[NGRAPH * POOLW];

// ---------------- prep: counts, scan, fill, dis ------------------------------
__global__ void zero_kernel(int n) {
    int i = blockIdx.x * blockDim.x + threadIdx.x;
    if (i < NGRAPH * POOLW) g_pool[i] = 0.0f;
    if (i < n) { g_cnt[i] = 0; g_fill[i] = 0; }
}

__global__ void count_kernel(const int* __restrict__ ei_col, int E) {
    int e = blockIdx.x * blockDim.x + threadIdx.x;
    if (e < E) atomicAdd(&g_cnt[ei_col[e]], 1);
}

__global__ __launch_bounds__(SCAN_T) void scan_kernel(int n) {
    __shared__ int ssum[SCAN_T];
    int tid = threadIdx.x;
    int chunk = (n + SCAN_T - 1) / SCAN_T;
    int lo = tid * chunk;
    int hi = min(lo + chunk, n);
    int s = 0;
    for (int i = lo; i < hi; i++) s += g_cnt[i];
    ssum[tid] = s;
    __syncthreads();
    for (int d = 1; d < SCAN_T; d <<= 1) {
        int v = (tid >= d) ? ssum[tid - d] : 0;
        __syncthreads();
        ssum[tid] += v;
        __syncthreads();
    }
    int base = (tid > 0) ? ssum[tid - 1] : 0;
    for (int i = lo; i < hi; i++) {
        g_off[i] = base;
        g_dis[i] = rsqrtf(1.0f + (float)g_cnt[i]);
        base += g_cnt[i];
    }
    if (tid == SCAN_T - 1) g_off[n] = base;
}

__global__ void fill_kernel(const int* __restrict__ ei, int E) {
    int e = blockIdx.x * blockDim.x + threadIdx.x;
    if (e < E) {
        int c = ei[E + e];
        int pos = g_off[c] + atomicAdd(&g_fill[c], 1);
        g_src[pos] = ei[e];
    }
}

// ---------------- TF32 tensor-core GEMM: hs = dis * (X @ W) ------------------
// block: 256 threads (8 warps), tile 128(M) x 128(N), K chunked by 32.
// warp w: rows [w*16, w*16+16), all 128 cols as 16 n8-tiles.
// mma.sync.m16n8k8 tf32. smem holds tf32 bit patterns.
#define XS 36    // sX row stride (floats): banks (4g + t4) conflict-free
#define WS 136   // sW row stride (floats): banks (8k + g)  conflict-free

__device__ __forceinline__ uint32_t f2tf(float f) {
    uint32_t r;
    asm("cvt.rna.tf32.f32 %0, %1;" : "=r"(r) : "f"(f));
    return r;
}

__global__ __launch_bounds__(256) void gemm_tf32_kernel(
    int xsel, const float* __restrict__ Xin, const float* __restrict__ W, int N)
{
    const float* X = (xsel == 0) ? Xin : (xsel == 1 ? g_x1 : g_x2);

    __shared__ uint32_t sX[128 * XS];   // [row][k] tf32
    __shared__ uint32_t sW[32 * WS];    // [k][col] tf32

    int tid  = threadIdx.x;
    int warp = tid >> 5;
    int lane = tid & 31;
    int g    = lane >> 2;    // group id 0..7
    int t4   = lane & 3;     // thread in group 0..3
    int row0 = blockIdx.x * 128;

    float c[16][4];
    #pragma unroll
    for (int nt = 0; nt < 16; nt++)
        { c[nt][0]=0.f; c[nt][1]=0.f; c[nt][2]=0.f; c[nt][3]=0.f; }

    #pragma unroll
    for (int kc = 0; kc < FEATN; kc += 32) {
        // stage X chunk 128x32 (1024 float4, 4/thread), convert to tf32
        #pragma unroll
        for (int i = 0; i < 4; i++) {
            int idx = tid + i * 256;
            int r   = idx >> 3;
            int c4  = (idx & 7) * 4;
            float4 v = make_float4(0.f, 0.f, 0.f, 0.f);
            int gr = row0 + r;
            if (gr < N) v = *(const float4*)(X + (long)gr * FEATN + kc + c4);
            sX[r * XS + c4 + 0] = f2tf(v.x);
            sX[r * XS + c4 + 1] = f2tf(v.y);
            sX[r * XS + c4 + 2] = f2tf(v.z);
            sX[r * XS + c4 + 3] = f2tf(v.w);
        }
        // stage W chunk 32x128
        #pragma unroll
        for (int i = 0; i < 4; i++) {
            int idx = tid + i * 256;
            int r   = idx >> 5;
            int c4  = (idx & 31) * 4;
            float4 v = *(const float4*)(W + (long)(kc + r) * FEATN + c4);
            sW[r * WS + c4 + 0] = f2tf(v.x);
            sW[r * WS + c4 + 1] = f2tf(v.y);
            sW[r * WS + c4 + 2] = f2tf(v.z);
            sW[r * WS + c4 + 3] = f2tf(v.w);
        }
        __syncthreads();

        #pragma unroll
        for (int k8 = 0; k8 < 32; k8 += 8) {
            int ar = warp * 16 + g;
            int ac = k8 + t4;
            uint32_t a0 = sX[ ar      * XS + ac    ];
            uint32_t a1 = sX[(ar + 8) * XS + ac    ];
            uint32_t a2 = sX[ ar      * XS + ac + 4];
            uint32_t a3 = sX[(ar + 8) * XS + ac + 4];
            #pragma unroll
            for (int nt = 0; nt < 16; nt++) {
                int bn = nt * 8 + g;
                uint32_t b0 = sW[(k8 + t4    ) * WS + bn];
                uint32_t b1 = sW[(k8 + t4 + 4) * WS + bn];
                asm volatile(
                    "mma.sync.aligned.m16n8k8.row.col.f32.tf32.tf32.f32 "
                    "{%0,%1,%2,%3}, {%4,%5,%6,%7}, {%8,%9}, {%0,%1,%2,%3};"
                    : "+f"(c[nt][0]), "+f"(c[nt][1]), "+f"(c[nt][2]), "+f"(c[nt][3])
                    : "r"(a0), "r"(a1), "r"(a2), "r"(a3), "r"(b0), "r"(b1));
            }
        }
        __syncthreads();
    }

    // epilogue: hs = dis * acc
    int r0 = row0 + warp * 16 + g;
    int r1 = r0 + 8;
    float d0 = (r0 < N) ? g_dis[r0] : 0.f;
    float d1 = (r1 < N) ? g_dis[r1] : 0.f;
    #pragma unroll
    for (int nt = 0; nt < 16; nt++) {
        int col = nt * 8 + 2 * t4;
        if (r0 < N) {
            float2 h0 = make_float2(c[nt][0] * d0, c[nt][1] * d0);
            *(float2*)(g_hs + (long)r0 * FEATN + col) = h0;
        }
        if (r1 < N) {
            float2 h1 = make_float2(c[nt][2] * d1, c[nt][3] * d1);
            *(float2*)(g_hs + (long)r1 * FEATN + col) = h1;
        }
    }
}

// ---------------- gather + finalize (fused) ----------------------------------
__global__ __launch_bounds__(256) void gather_kernel(
    const float* __restrict__ b, int outsel, float* __restrict__ x3out,
    const int* __restrict__ batch, int N, int pool_off)
{
    long idx = (long)blockIdx.x * blockDim.x + threadIdx.x;
    int i = (int)(idx >> 5);
    if (i >= N) return;
    int lane = (int)(idx & 31);
    int l4 = lane * 4;

    float* xnext = (outsel == 1) ? g_x1 : (outsel == 2 ? g_x2 : x3out);

    float4 accA = *(const float4*)(g_hs + (long)i * FEATN + l4);
    float4 accB = make_float4(0.f, 0.f, 0.f, 0.f);

    int s0 = g_off[i];
    int s1 = g_off[i + 1];
    int k = s0;
    for (; k + 8 <= s1; k += 8) {
        int r0 = g_src[k],   r1 = g_src[k+1], r2 = g_src[k+2], r3 = g_src[k+3];
        int r4 = g_src[k+4], r5 = g_src[k+5], r6 = g_src[k+6], r7 = g_src[k+7];
        float4 v0 = *(const float4*)(g_hs + (long)r0 * FEATN + l4);
        float4 v1 = *(const float4*)(g_hs + (long)r1 * FEATN + l4);
        float4 v2 = *(const float4*)(g_hs + (long)r2 * FEATN + l4);
        float4 v3 = *(const float4*)(g_hs + (long)r3 * FEATN + l4);
        float4 v4 = *(const float4*)(g_hs + (long)r4 * FEATN + l4);
        float4 v5 = *(const float4*)(g_hs + (long)r5 * FEATN + l4);
        float4 v6 = *(const float4*)(g_hs + (long)r6 * FEATN + l4);
        float4 v7 = *(const float4*)(g_hs + (long)r7 * FEATN + l4);
        accA.x += (v0.x + v1.x) + (v2.x + v3.x);
        accA.y += (v0.y + v1.y) + (v2.y + v3.y);
        accA.z += (v0.z + v1.z) + (v2.z + v3.z);
        accA.w += (v0.w + v1.w) + (v2.w + v3.w);
        accB.x += (v4.x + v5.x) + (v6.x + v7.x);
        accB.y += (v4.y + v5.y) + (v6.y + v7.y);
        accB.z += (v4.z + v5.z) + (v6.z + v7.z);
        accB.w += (v4.w + v5.w) + (v6.w + v7.w);
    }
    for (; k + 4 <= s1; k += 4) {
        int r0 = g_src[k], r1 = g_src[k+1], r2 = g_src[k+2], r3 = g_src[k+3];
        float4 v0 = *(const float4*)(g_hs + (long)r0 * FEATN + l4);
        float4 v1 = *(const float4*)(g_hs + (long)r1 * FEATN + l4);
        float4 v2 = *(const float4*)(g_hs + (long)r2 * FEATN + l4);
        float4 v3 = *(const float4*)(g_hs + (long)r3 * FEATN + l4);
        accA.x += (v0.x + v1.x) + (v2.x + v3.x);
        accA.y += (v0.y + v1.y) + (v2.y + v3.y);
        accA.z += (v0.z + v1.z) + (v2.z + v3.z);
        accA.w += (v0.w + v1.w) + (v2.w + v3.w);
    }
    for (; k < s1; k++) {
        int r = g_src[k];
        float4 v = *(const float4*)(g_hs + (long)r * FEATN + l4);
        accB.x += v.x; accB.y += v.y; accB.z += v.z; accB.w += v.w;
    }
    accA.x += accB.x; accA.y += accB.y; accA.z += accB.z; accA.w += accB.w;

    float d = g_dis[i];
    float4 bv = *(const float4*)(b + l4);
    float4 o;
    o.x = fmaxf(accA.x * d + bv.x, 0.f);
    o.y = fmaxf(accA.y * d + bv.y, 0.f);
    o.z = fmaxf(accA.z * d + bv.z, 0.f);
    o.w = fmaxf(accA.w * d + bv.w, 0.f);
    *(float4*)(xnext + (long)i * FEATN + l4) = o;

    int g = batch[i];
    float* p = g_pool + (long)g * POOLW + pool_off + l4;
    atomicAdd(p + 0, o.x);
    atomicAdd(p + 1, o.y);
    atomicAdd(p + 2, o.z);
    atomicAdd(p + 3, o.w);
}

__global__ void copy_pool_kernel(float* __restrict__ out) {
    int i = blockIdx.x * blockDim.x + threadIdx.x;
    if (i < NGRAPH * POOLW) out[i] = g_pool[i];
}

// ---------------- launch ------------------------------------------------------
extern "C" void kernel_launch(void* const* d_in, const int* in_sizes, int n_in,
                              void* d_out, int out_size)
{
    const float* x     = (const float*)d_in[0];
    const int*   ei    = (const int*)d_in[1];    // int32 (JAX x64 disabled)
    const int*   batch = (const int*)d_in[2];
    const float* W0    = (const float*)d_in[3];
    const float* b0    = (const float*)d_in[4];
    const float* W1    = (const float*)d_in[5];
    const float* b1    = (const float*)d_in[6];
    const float* W2    = (const float*)d_in[7];
    const float* b2    = (const float*)d_in[8];

    int N = in_sizes[0] / FEATN;     // 50000
    int E = in_sizes[1] / 2;         // 800000
    int pool_elems = NGRAPH * POOLW; // 49152

    float* out = (float*)d_out;
    float* x3  = out + pool_elems;

    // prep: zero, count, scan(+dis), fill  (CSR built once, reused 3x)
    zero_kernel<<<(N + 255) / 256, 256>>>(N);
    count_kernel<<<(E + 255) / 256, 256>>>(ei + E, E);
    scan_kernel<<<1, SCAN_T>>>(N);
    fill_kernel<<<(E + 255) / 256, 256>>>(ei, E);

    int gemm_blocks  = (N + 127) / 128;
    long gat_threads = (long)N * 32;
    int gat_blocks   = (int)((gat_threads + 255) / 256);

    // layer 1
    gemm_tf32_kernel<<<gemm_blocks, 256>>>(0, x, W0, N);
    gather_kernel<<<gat_blocks, 256>>>(b0, 1, nullptr, batch, N, 0);

    // layer 2
    gemm_tf32_kernel<<<gemm_blocks, 256>>>(1, nullptr, W1, N);
    gather_kernel<<<gat_blocks, 256>>>(b1, 2, nullptr, batch, N, 128);

    // layer 3
    gemm_tf32_kernel<<<gemm_blocks, 256>>>(2, nullptr, W2, N);
    gather_kernel<<<gat_blocks, 256>>>(b2, 3, x3, batch, N, 256);

    // pool -> d_out (plain stores only)
    copy_pool_kernel<<<(pool_elems + 255) / 256, 256>>>(out);
}

// round 11
// speedup vs baseline: 1.6853x; 1.1125x over previous
#include <cuda_runtime.h>
#include <cuda_bf16.h>
#include <cstdint>

#define NMAX   50000
#define EMAX   800000
#define FEATN  128
#define POOLW  384   // 3*128
#define NGRAPH 128
#define SCAN_T 1024

// ---------------- scratch (static device globals; no allocation) -------------
__device__ __align__(256) float g_dis [NMAX];
__device__ __align__(256) int   g_cnt [NMAX];
__device__ __align__(256) int   g_fill[NMAX];
__device__ __align__(256) int   g_off [NMAX + 1];
__device__ __align__(256) int   g_gstart[NGRAPH + 1];
__device__ __align__(256) int   g_src [EMAX];
__device__ __align__(256) float g_hs  [NMAX * FEATN];   // dis[r] * (x @ W)
__device__ __align__(256) float g_x1  [NMAX * FEATN];
__device__ __align__(256) float g_x2  [NMAX * FEATN];

// ---------------- prep: counts, scan, fill, dis, graph bounds ----------------
__global__ void zero_kernel(int n) {
    int i = blockIdx.x * blockDim.x + threadIdx.x;
    if (i < n) { g_cnt[i] = 0; g_fill[i] = 0; }
}

__global__ void count_kernel(const int* __restrict__ ei_col, int E) {
    int e = blockIdx.x * blockDim.x + threadIdx.x;
    if (e < E) atomicAdd(&g_cnt[ei_col[e]], 1);
}

__global__ __launch_bounds__(SCAN_T) void scan_kernel(int n) {
    __shared__ int ssum[SCAN_T];
    int tid = threadIdx.x;
    int chunk = (n + SCAN_T - 1) / SCAN_T;
    int lo = tid * chunk;
    int hi = min(lo + chunk, n);
    int s = 0;
    for (int i = lo; i < hi; i++) s += g_cnt[i];
    ssum[tid] = s;
    __syncthreads();
    for (int d = 1; d < SCAN_T; d <<= 1) {
        int v = (tid >= d) ? ssum[tid - d] : 0;
        __syncthreads();
        ssum[tid] += v;
        __syncthreads();
    }
    int base = (tid > 0) ? ssum[tid - 1] : 0;
    for (int i = lo; i < hi; i++) {
        g_off[i] = base;
        g_dis[i] = rsqrtf(1.0f + (float)g_cnt[i]);
        base += g_cnt[i];
    }
    if (tid == SCAN_T - 1) g_off[n] = base;
}

__global__ void fill_kernel(const int* __restrict__ ei, int E) {
    int e = blockIdx.x * blockDim.x + threadIdx.x;
    if (e < E) {
        int c = ei[E + e];
        int pos = g_off[c] + atomicAdd(&g_fill[c], 1);
        g_src[pos] = ei[e];
    }
}

// batch is sorted: find contiguous [start, end) per graph
__global__ void gbound_kernel(const int* __restrict__ batch, int N) {
    int i = blockIdx.x * blockDim.x + threadIdx.x;
    if (i >= N) return;
    int b = batch[i];
    if (i == 0) {
        for (int g = 0; g <= b; g++) g_gstart[g] = 0;
    } else {
        int pb = batch[i - 1];
        for (int g = pb + 1; g <= b; g++) g_gstart[g] = i;
    }
    if (i == N - 1) {
        for (int g = b + 1; g <= NGRAPH; g++) g_gstart[g] = N;
    }
}

// ---------------- TF32 tensor-core GEMM: hs = dis * (X @ W) ------------------
#define XS 36    // sX row stride (floats): conflict-free
#define WS 136   // sW row stride (floats): conflict-free

__device__ __forceinline__ uint32_t f2tf(float f) {
    uint32_t r;
    asm("cvt.rna.tf32.f32 %0, %1;" : "=r"(r) : "f"(f));
    return r;
}

__global__ __launch_bounds__(256) void gemm_tf32_kernel(
    int xsel, const float* __restrict__ Xin, const float* __restrict__ W, int N)
{
    const float* X = (xsel == 0) ? Xin : (xsel == 1 ? g_x1 : g_x2);

    __shared__ uint32_t sX[128 * XS];   // [row][k] tf32
    __shared__ uint32_t sW[32 * WS];    // [k][col] tf32

    int tid  = threadIdx.x;
    int warp = tid >> 5;
    int lane = tid & 31;
    int g    = lane >> 2;
    int t4   = lane & 3;
    int row0 = blockIdx.x * 128;

    float c[16][4];
    #pragma unroll
    for (int nt = 0; nt < 16; nt++)
        { c[nt][0]=0.f; c[nt][1]=0.f; c[nt][2]=0.f; c[nt][3]=0.f; }

    #pragma unroll
    for (int kc = 0; kc < FEATN; kc += 32) {
        #pragma unroll
        for (int i = 0; i < 4; i++) {
            int idx = tid + i * 256;
            int r   = idx >> 3;
            int c4  = (idx & 7) * 4;
            float4 v = make_float4(0.f, 0.f, 0.f, 0.f);
            int gr = row0 + r;
            if (gr < N) v = *(const float4*)(X + (long)gr * FEATN + kc + c4);
            sX[r * XS + c4 + 0] = f2tf(v.x);
            sX[r * XS + c4 + 1] = f2tf(v.y);
            sX[r * XS + c4 + 2] = f2tf(v.z);
            sX[r * XS + c4 + 3] = f2tf(v.w);
        }
        #pragma unroll
        for (int i = 0; i < 4; i++) {
            int idx = tid + i * 256;
            int r   = idx >> 5;
            int c4  = (idx & 31) * 4;
            float4 v = *(const float4*)(W + (long)(kc + r) * FEATN + c4);
            sW[r * WS + c4 + 0] = f2tf(v.x);
            sW[r * WS + c4 + 1] = f2tf(v.y);
            sW[r * WS + c4 + 2] = f2tf(v.z);
            sW[r * WS + c4 + 3] = f2tf(v.w);
        }
        __syncthreads();

        #pragma unroll
        for (int k8 = 0; k8 < 32; k8 += 8) {
            int ar = warp * 16 + g;
            int ac = k8 + t4;
            uint32_t a0 = sX[ ar      * XS + ac    ];
            uint32_t a1 = sX[(ar + 8) * XS + ac    ];
            uint32_t a2 = sX[ ar      * XS + ac + 4];
            uint32_t a3 = sX[(ar + 8) * XS + ac + 4];
            #pragma unroll
            for (int nt = 0; nt < 16; nt++) {
                int bn = nt * 8 + g;
                uint32_t b0 = sW[(k8 + t4    ) * WS + bn];
                uint32_t b1 = sW[(k8 + t4 + 4) * WS + bn];
                asm volatile(
                    "mma.sync.aligned.m16n8k8.row.col.f32.tf32.tf32.f32 "
                    "{%0,%1,%2,%3}, {%4,%5,%6,%7}, {%8,%9}, {%0,%1,%2,%3};"
                    : "+f"(c[nt][0]), "+f"(c[nt][1]), "+f"(c[nt][2]), "+f"(c[nt][3])
                    : "r"(a0), "r"(a1), "r"(a2), "r"(a3), "r"(b0), "r"(b1));
            }
        }
        __syncthreads();
    }

    int r0 = row0 + warp * 16 + g;
    int r1 = r0 + 8;
    float d0 = (r0 < N) ? g_dis[r0] : 0.f;
    float d1 = (r1 < N) ? g_dis[r1] : 0.f;
    #pragma unroll
    for (int nt = 0; nt < 16; nt++) {
        int col = nt * 8 + 2 * t4;
        if (r0 < N) {
            float2 h0 = make_float2(c[nt][0] * d0, c[nt][1] * d0);
            *(float2*)(g_hs + (long)r0 * FEATN + col) = h0;
        }
        if (r1 < N) {
            float2 h1 = make_float2(c[nt][2] * d1, c[nt][3] * d1);
            *(float2*)(g_hs + (long)r1 * FEATN + col) = h1;
        }
    }
}

// ---------------- gather + finalize (fused, atomic-free) ---------------------
// warp per node: out = relu(dis[i]*(sum_in hs[r] + hs[i]) + b)
__global__ __launch_bounds__(256) void gather_kernel(
    const float* __restrict__ b, int outsel, float* __restrict__ x3out, int N)
{
    long idx = (long)blockIdx.x * blockDim.x + threadIdx.x;
    int i = (int)(idx >> 5);
    if (i >= N) return;
    int lane = (int)(idx & 31);
    int l4 = lane * 4;

    float* xnext = (outsel == 1) ? g_x1 : (outsel == 2 ? g_x2 : x3out);

    float4 accA = *(const float4*)(g_hs + (long)i * FEATN + l4);
    float4 accB = make_float4(0.f, 0.f, 0.f, 0.f);

    int s0 = g_off[i];
    int s1 = g_off[i + 1];
    int k = s0;
    for (; k + 8 <= s1; k += 8) {
        int r0 = g_src[k],   r1 = g_src[k+1], r2 = g_src[k+2], r3 = g_src[k+3];
        int r4 = g_src[k+4], r5 = g_src[k+5], r6 = g_src[k+6], r7 = g_src[k+7];
        float4 v0 = *(const float4*)(g_hs + (long)r0 * FEATN + l4);
        float4 v1 = *(const float4*)(g_hs + (long)r1 * FEATN + l4);
        float4 v2 = *(const float4*)(g_hs + (long)r2 * FEATN + l4);
        float4 v3 = *(const float4*)(g_hs + (long)r3 * FEATN + l4);
        float4 v4 = *(const float4*)(g_hs + (long)r4 * FEATN + l4);
        float4 v5 = *(const float4*)(g_hs + (long)r5 * FEATN + l4);
        float4 v6 = *(const float4*)(g_hs + (long)r6 * FEATN + l4);
        float4 v7 = *(const float4*)(g_hs + (long)r7 * FEATN + l4);
        accA.x += (v0.x + v1.x) + (v2.x + v3.x);
        accA.y += (v0.y + v1.y) + (v2.y + v3.y);
        accA.z += (v0.z + v1.z) + (v2.z + v3.z);
        accA.w += (v0.w + v1.w) + (v2.w + v3.w);
        accB.x += (v4.x + v5.x) + (v6.x + v7.x);
        accB.y += (v4.y + v5.y) + (v6.y + v7.y);
        accB.z += (v4.z + v5.z) + (v6.z + v7.z);
        accB.w += (v4.w + v5.w) + (v6.w + v7.w);
    }
    for (; k + 4 <= s1; k += 4) {
        int r0 = g_src[k], r1 = g_src[k+1], r2 = g_src[k+2], r3 = g_src[k+3];
        float4 v0 = *(const float4*)(g_hs + (long)r0 * FEATN + l4);
        float4 v1 = *(const float4*)(g_hs + (long)r1 * FEATN + l4);
        float4 v2 = *(const float4*)(g_hs + (long)r2 * FEATN + l4);
        float4 v3 = *(const float4*)(g_hs + (long)r3 * FEATN + l4);
        accA.x += (v0.x + v1.x) + (v2.x + v3.x);
        accA.y += (v0.y + v1.y) + (v2.y + v3.y);
        accA.z += (v0.z + v1.z) + (v2.z + v3.z);
        accA.w += (v0.w + v1.w) + (v2.w + v3.w);
    }
    for (; k < s1; k++) {
        int r = g_src[k];
        float4 v = *(const float4*)(g_hs + (long)r * FEATN + l4);
        accB.x += v.x; accB.y += v.y; accB.z += v.z; accB.w += v.w;
    }
    accA.x += accB.x; accA.y += accB.y; accA.z += accB.z; accA.w += accB.w;

    float d = g_dis[i];
    float4 bv = *(const float4*)(b + l4);
    float4 o;
    o.x = fmaxf(accA.x * d + bv.x, 0.f);
    o.y = fmaxf(accA.y * d + bv.y, 0.f);
    o.z = fmaxf(accA.z * d + bv.z, 0.f);
    o.w = fmaxf(accA.w * d + bv.w, 0.f);
    *(float4*)(xnext + (long)i * FEATN + l4) = o;
}

// ---------------- segment-sum pooling (sorted batch, plain stores) -----------
// block per graph, 128 threads = 128 feats; writes directly into d_out pool.
__global__ __launch_bounds__(128) void segpool_kernel(
    int xsel, const float* __restrict__ x3out,
    float* __restrict__ outp, int pool_off)
{
    const float* X = (xsel == 1) ? g_x1 : (xsel == 2 ? g_x2 : x3out);
    int g = blockIdx.x;
    int t = threadIdx.x;
    int s = g_gstart[g];
    int e = g_gstart[g + 1];
    float a0 = 0.f, a1 = 0.f, a2 = 0.f, a3 = 0.f;
    int i = s;
    for (; i + 4 <= e; i += 4) {
        a0 += X[(long)(i    ) * FEATN + t];
        a1 += X[(long)(i + 1) * FEATN + t];
        a2 += X[(long)(i + 2) * FEATN + t];
        a3 += X[(long)(i + 3) * FEATN + t];
    }
    for (; i < e; i++) a0 += X[(long)i * FEATN + t];
    outp[(long)g * POOLW + pool_off + t] = (a0 + a1) + (a2 + a3);
}

// ---------------- launch ------------------------------------------------------
extern "C" void kernel_launch(void* const* d_in, const int* in_sizes, int n_in,
                              void* d_out, int out_size)
{
    const float* x     = (const float*)d_in[0];
    const int*   ei    = (const int*)d_in[1];    // int32 (JAX x64 disabled)
    const int*   batch = (const int*)d_in[2];
    const float* W0    = (const float*)d_in[3];
    const float* b0    = (const float*)d_in[4];
    const float* W1    = (const float*)d_in[5];
    const float* b1    = (const float*)d_in[6];
    const float* W2    = (const float*)d_in[7];
    const float* b2    = (const float*)d_in[8];

    int N = in_sizes[0] / FEATN;     // 50000
    int E = in_sizes[1] / 2;         // 800000
    int pool_elems = NGRAPH * POOLW; // 49152

    float* out = (float*)d_out;
    float* x3  = out + pool_elems;

    // prep: zero, count, scan(+dis), fill, graph bounds (CSR built once)
    zero_kernel<<<(N + 255) / 256, 256>>>(N);
    count_kernel<<<(E + 255) / 256, 256>>>(ei + E, E);
    scan_kernel<<<1, SCAN_T>>>(N);
    fill_kernel<<<(E + 255) / 256, 256>>>(ei, E);
    gbound_kernel<<<(N + 255) / 256, 256>>>(batch, N);

    int gemm_blocks  = (N + 127) / 128;
    long gat_threads = (long)N * 32;
    int gat_blocks   = (int)((gat_threads + 255) / 256);

    // layer 1
    gemm_tf32_kernel<<<gemm_blocks, 256>>>(0, x, W0, N);
    gather_kernel<<<gat_blocks, 256>>>(b0, 1, nullptr, N);
    segpool_kernel<<<NGRAPH, 128>>>(1, nullptr, out, 0);

    // layer 2
    gemm_tf32_kernel<<<gemm_blocks, 256>>>(1, nullptr, W1, N);
    gather_kernel<<<gat_blocks, 256>>>(b1, 2, nullptr, N);
    segpool_kernel<<<NGRAPH, 128>>>(2, nullptr, out, 128);

    // layer 3
    gemm_tf32_kernel<<<gemm_blocks, 256>>>(2, nullptr, W2, N);
    gather_kernel<<<gat_blocks, 256>>>(b2, 3, x3, N);
    segpool_kernel<<<NGRAPH, 128>>>(3, x3, out, 256);
}